// round 1
// baseline (speedup 1.0000x reference)
#include <cuda_runtime.h>
#include <math.h>

#define NEG_INF (-1e9f)

// Problem constants (fixed by the dataset)
#define Bsz 32
#define LQ  1024
#define LK  1024
#define DIM 1024

// Scratch (allocation-free rule: __device__ globals)
// combined: [B*Lq, 2D] row-major. cols [0,D) = mix, cols [D,2D) = q
__device__ float g_combined[(long long)Bsz * LQ * 2 * DIM];
// weights: [B, Lq, Lk]
__device__ float g_weights[(long long)Bsz * LQ * LK];

// ---------------------------------------------------------------------------
// Generic tiled SGEMM: C[m,n] = sum_k A[m,k] * op(B)
//   TRANS_B=1: op(B)[k,n] = B[n,k]  (B is N x K row-major; dot of rows)
//   TRANS_B=0: op(B)[k,n] = B[k,n]  (B is K x N row-major)
// EPI: 0 = plain store, 1 = length-mask -> NEG_INF, 2 = tanh
// Tile: 128x128x8, 256 threads, 8x8 per-thread microtile.
// All dims assumed multiples of 128 / 8 (true for this problem).
// ---------------------------------------------------------------------------
template <int TRANS_B, int EPI>
__global__ __launch_bounds__(256)
void gemm_kernel(const float* __restrict__ A, const float* __restrict__ B,
                 float* __restrict__ C,
                 int M, int N, int K,
                 int lda, int ldb, int ldc,
                 long long strideA, long long strideB, long long strideC,
                 const int* __restrict__ ql, const int* __restrict__ cl)
{
    const int bz = blockIdx.z;
    A += (long long)bz * strideA;
    B += (long long)bz * strideB;
    C += (long long)bz * strideC;

    __shared__ float As[8][128];
    __shared__ float Bs[8][128];

    const int tid = threadIdx.x;
    const int tx = tid & 15;   // 0..15 -> col group
    const int ty = tid >> 4;   // 0..15 -> row group
    const int m0 = blockIdx.y * 128;
    const int n0 = blockIdx.x * 128;

    float acc[8][8];
#pragma unroll
    for (int i = 0; i < 8; i++)
#pragma unroll
        for (int j = 0; j < 8; j++) acc[i][j] = 0.f;

    // A-tile load mapping (also used for B when TRANS_B): row = tid/2, k4 = (tid&1)*4
    const int a_row = tid >> 1;
    const int a_k4  = (tid & 1) * 4;
    // B-tile load mapping for NN: k = tid/32, n4 = (tid&31)*4
    const int bn_k  = tid >> 5;
    const int bn_n4 = (tid & 31) * 4;

    for (int k0 = 0; k0 < K; k0 += 8) {
        {
            float4 v = *(const float4*)&A[(long long)(m0 + a_row) * lda + k0 + a_k4];
            As[a_k4 + 0][a_row] = v.x;
            As[a_k4 + 1][a_row] = v.y;
            As[a_k4 + 2][a_row] = v.z;
            As[a_k4 + 3][a_row] = v.w;
        }
        if (TRANS_B) {
            float4 v = *(const float4*)&B[(long long)(n0 + a_row) * ldb + k0 + a_k4];
            Bs[a_k4 + 0][a_row] = v.x;
            Bs[a_k4 + 1][a_row] = v.y;
            Bs[a_k4 + 2][a_row] = v.z;
            Bs[a_k4 + 3][a_row] = v.w;
        } else {
            float4 v = *(const float4*)&B[(long long)(k0 + bn_k) * ldb + n0 + bn_n4];
            *(float4*)&Bs[bn_k][bn_n4] = v;
        }
        __syncthreads();

#pragma unroll
        for (int kk = 0; kk < 8; kk++) {
            float a[8], b[8];
#pragma unroll
            for (int i = 0; i < 8; i++) a[i] = As[kk][ty * 8 + i];
#pragma unroll
            for (int j = 0; j < 8; j++) b[j] = Bs[kk][tx * 8 + j];
#pragma unroll
            for (int i = 0; i < 8; i++)
#pragma unroll
                for (int j = 0; j < 8; j++) acc[i][j] += a[i] * b[j];
        }
        __syncthreads();
    }

    int qlen = 0, clen = 0;
    if (EPI == 1) { qlen = ql[bz]; clen = cl[bz]; }

#pragma unroll
    for (int i = 0; i < 8; i++) {
        const int gm = m0 + ty * 8 + i;
#pragma unroll
        for (int j = 0; j < 8; j++) {
            const int gn = n0 + tx * 8 + j;
            float v = acc[i][j];
            if (EPI == 1) { if (gm >= qlen || gn >= clen) v = NEG_INF; }
            if (EPI == 2) v = tanhf(v);
            C[(long long)gm * ldc + gn] = v;
        }
    }
}

// ---------------------------------------------------------------------------
// Row softmax over Lk=1024, one block (256 threads) per row.
// Fully-masked rows (all -1e9) correctly produce uniform 1/Lk, matching jax.
// ---------------------------------------------------------------------------
__global__ __launch_bounds__(256)
void softmax_kernel(const float* __restrict__ scores, float* __restrict__ weights)
{
    const long long row = blockIdx.x;
    const float* s = scores + row * LK;
    float* w = weights + row * LK;
    const int t = threadIdx.x;

    float v[4];
    float lmax = -INFINITY;
#pragma unroll
    for (int c = 0; c < 4; c++) {
        v[c] = s[t + c * 256];
        lmax = fmaxf(lmax, v[c]);
    }

    __shared__ float red[8];
#pragma unroll
    for (int o = 16; o > 0; o >>= 1) lmax = fmaxf(lmax, __shfl_xor_sync(0xffffffffu, lmax, o));
    if ((t & 31) == 0) red[t >> 5] = lmax;
    __syncthreads();
    if (t < 32) {
        float m = (t < 8) ? red[t] : -INFINITY;
#pragma unroll
        for (int o = 4; o > 0; o >>= 1) m = fmaxf(m, __shfl_xor_sync(0xffffffffu, m, o));
        if (t == 0) red[0] = m;
    }
    __syncthreads();
    const float m = red[0];

    float lsum = 0.f;
#pragma unroll
    for (int c = 0; c < 4; c++) {
        v[c] = __expf(v[c] - m);
        lsum += v[c];
    }
#pragma unroll
    for (int o = 16; o > 0; o >>= 1) lsum += __shfl_xor_sync(0xffffffffu, lsum, o);
    __shared__ float red2[8];
    if ((t & 31) == 0) red2[t >> 5] = lsum;
    __syncthreads();
    if (t < 32) {
        float x = (t < 8) ? red2[t] : 0.f;
#pragma unroll
        for (int o = 4; o > 0; o >>= 1) x += __shfl_xor_sync(0xffffffffu, x, o);
        if (t == 0) red2[0] = x;
    }
    __syncthreads();
    const float inv = 1.0f / red2[0];

#pragma unroll
    for (int c = 0; c < 4; c++) w[t + c * 256] = v[c] * inv;
}

// ---------------------------------------------------------------------------
// kernel_launch
// Inputs (metadata order): query [B,Lq,D] f32, context [B,Lk,D] f32,
//   query_lengths [B] i32, context_lengths [B] i32,
//   W_in [D,D] f32, W_out [D,2D] f32
// Output: output [B,Lq,D] followed by scores_m [B,Lq,Lk]  (f32)
// ---------------------------------------------------------------------------
extern "C" void kernel_launch(void* const* d_in, const int* in_sizes, int n_in,
                              void* d_out, int out_size)
{
    const float* query   = (const float*)d_in[0];
    const float* context = (const float*)d_in[1];
    const int*   ql      = (const int*)d_in[2];
    const int*   cl      = (const int*)d_in[3];
    const float* W_in    = (const float*)d_in[4];
    const float* W_out   = (const float*)d_in[5];

    float* out        = (float*)d_out;                                   // [B,Lq,D]
    float* scores_out = out + (long long)Bsz * LQ * DIM;                 // [B,Lq,Lk]

    float* combined = nullptr;
    float* weights  = nullptr;
    cudaGetSymbolAddress((void**)&combined, g_combined);
    cudaGetSymbolAddress((void**)&weights,  g_weights);

    const long long M_all = (long long)Bsz * LQ;   // 32768

    // K1: q = query @ W_in^T  -> combined cols [D, 2D)
    {
        dim3 grid(DIM / 128, (unsigned)(M_all / 128), 1);
        gemm_kernel<1, 0><<<grid, 256>>>(
            query, W_in, combined + DIM,
            (int)M_all, DIM, DIM,
            DIM, DIM, 2 * DIM,
            0, 0, 0, nullptr, nullptr);
    }

    // K2: scores[b] = q[b] @ context[b]^T, mask -> scores_out (output #2)
    {
        dim3 grid(LK / 128, LQ / 128, Bsz);
        gemm_kernel<1, 1><<<grid, 256>>>(
            combined + DIM, context, scores_out,
            LQ, LK, DIM,
            2 * DIM, DIM, LK,
            (long long)LQ * 2 * DIM, (long long)LK * DIM, (long long)LQ * LK,
            ql, cl);
    }

    // K3: softmax rows
    softmax_kernel<<<(unsigned)M_all, 256>>>(scores_out, weights);

    // K4: mix[b] = weights[b] @ context[b]  -> combined cols [0, D)
    {
        dim3 grid(DIM / 128, LQ / 128, Bsz);
        gemm_kernel<0, 0><<<grid, 256>>>(
            weights, context, combined,
            LQ, DIM, LK,
            LK, DIM, 2 * DIM,
            (long long)LQ * LK, (long long)LK * DIM, (long long)LQ * 2 * DIM,
            nullptr, nullptr);
    }

    // K5: out = tanh(combined @ W_out^T)
    {
        dim3 grid(DIM / 128, (unsigned)(M_all / 128), 1);
        gemm_kernel<1, 2><<<grid, 256>>>(
            combined, W_out, out,
            (int)M_all, DIM, 2 * DIM,
            2 * DIM, 2 * DIM, DIM,
            0, 0, 0, nullptr, nullptr);
    }
}

// round 3
// speedup vs baseline: 1.5602x; 1.5602x over previous
#include <cuda_runtime.h>
#include <cuda_bf16.h>
#include <stdint.h>
#include <math.h>

#define NEG_INF (-1e9f)

#define Bsz 32
#define LQ  1024
#define LK  1024
#define DIM 1024

// ---------------------------------------------------------------------------
// Scratch (__device__ globals; allocation-free rule)
// ---------------------------------------------------------------------------
__device__ float g_combined[(long long)Bsz * LQ * 2 * DIM];  // [32768, 2048] mix|q
__device__ float g_weights[(long long)Bsz * LQ * LK];        // [32,1024,1024]
__device__ float g_ctxT[(long long)Bsz * DIM * LK];          // [32, D, Lk]

// ---------------------------------------------------------------------------
#define SW128(off) ((off) ^ (((off) >> 3) & 0x70))

__device__ __forceinline__ uint32_t smem_u32(const void* p) {
    uint32_t a;
    asm("{ .reg .u64 t; cvta.to.shared.u64 t, %1; cvt.u32.u64 %0, t; }"
        : "=r"(a) : "l"(p));
    return a;
}

__device__ __forceinline__ void ldsm4(uint32_t* r, uint32_t addr) {
    asm volatile("ldmatrix.sync.aligned.m8n8.x4.shared.b16 {%0,%1,%2,%3}, [%4];"
                 : "=r"(r[0]), "=r"(r[1]), "=r"(r[2]), "=r"(r[3]) : "r"(addr));
}

__device__ __forceinline__ void mma16816(float* c, const uint32_t* a,
                                         uint32_t b0, uint32_t b1) {
    asm volatile(
        "mma.sync.aligned.m16n8k16.row.col.f32.bf16.bf16.f32 "
        "{%0,%1,%2,%3}, {%4,%5,%6,%7}, {%8,%9}, {%0,%1,%2,%3};"
        : "+f"(c[0]), "+f"(c[1]), "+f"(c[2]), "+f"(c[3])
        : "r"(a[0]), "r"(a[1]), "r"(a[2]), "r"(a[3]), "r"(b0), "r"(b1));
}

// ---------------------------------------------------------------------------
// Tile geometry: CTA 128x128, K-chunk 64 (bf16), 256 threads (8 warps, 2x4)
// SMEM stage: Ahi|Alo|Bhi|Blo, each 128x64 bf16 = 16KB (SW128 128B rows)
// ---------------------------------------------------------------------------
#define TM 128
#define TN 128
#define KC 64
#define T_BYTES   16384
#define OFF_AHI   0
#define OFF_ALO   16384
#define OFF_BHI   32768
#define OFF_BLO   49152
#define STAGE     65536
#define SM_TOTAL  (2 * STAGE)   // 131072

// Convert 8 fp32 -> hi/lo bf16 and store 16B each to swizzled smem
__device__ __forceinline__ void cvt_store8(float4 v0, float4 v1,
                                           char* hi_base, char* lo_base, uint32_t sw) {
    float x[8] = {v0.x, v0.y, v0.z, v0.w, v1.x, v1.y, v1.z, v1.w};
    uint32_t h[4], l[4];
#pragma unroll
    for (int i = 0; i < 4; i++) {
        float a = x[2 * i], b = x[2 * i + 1];
        __nv_bfloat162 hp = __floats2bfloat162_rn(a, b);
        h[i] = *reinterpret_cast<uint32_t*>(&hp);
        float2 hf = __bfloat1622float2(hp);
        __nv_bfloat162 lp = __floats2bfloat162_rn(a - hf.x, b - hf.y);
        l[i] = *reinterpret_cast<uint32_t*>(&lp);
    }
    *reinterpret_cast<uint4*>(hi_base + sw) = make_uint4(h[0], h[1], h[2], h[3]);
    *reinterpret_cast<uint4*>(lo_base + sw) = make_uint4(l[0], l[1], l[2], l[3]);
}

// ---------------------------------------------------------------------------
// split-bf16 mma.sync GEMM: C[m,n] = sum_k A[m,k]*B[n,k]  (both K-major)
// EPI: 0 plain, 1 length-mask, 2 tanh
// ---------------------------------------------------------------------------
template <int EPI>
__global__ __launch_bounds__(256, 1)
void mma_gemm(const float* __restrict__ A, const float* __restrict__ B,
              float* __restrict__ C, int K,
              int lda, int ldb, int ldc,
              long long sA, long long sB, long long sC,
              const int* __restrict__ ql, const int* __restrict__ cl)
{
    extern __shared__ char smem[];
    const uint32_t sb = smem_u32(smem);
    const int tid  = threadIdx.x;
    const int wid  = tid >> 5;
    const int lane = tid & 31;
    const int bz = blockIdx.z;
    const int m0 = blockIdx.y * TM;
    const int n0 = blockIdx.x * TN;

    A += (long long)bz * sA;
    B += (long long)bz * sB;
    C += (long long)bz * sC;

    // fill mapping: thread -> (row = tid/2, col half = (tid&1)*32), 4 chunks of 8
    const int lrow  = tid >> 1;
    const int lhalf = (tid & 1) * 32;
    const float* Ag = A + (long long)(m0 + lrow) * lda + lhalf;
    const float* Bg = B + (long long)(n0 + lrow) * ldb + lhalf;
    const uint32_t fill_base = (uint32_t)(lrow * 128 + lhalf * 2);

    // warp tile: 64x32
    const int wm = (wid & 1) * 64;
    const int wn = (wid >> 1) * 32;
    // ldmatrix lane constants
    const int lrow8 = (lane & 7) + ((lane >> 3) & 1) * 8;  // row within 16
    const int lk16  = ((lane >> 4) & 1) * 16;              // k-half bytes

    float acc[4][4][4];
#pragma unroll
    for (int mt = 0; mt < 4; mt++)
#pragma unroll
        for (int nt = 0; nt < 4; nt++)
#pragma unroll
            for (int i = 0; i < 4; i++) acc[mt][nt][i] = 0.f;

    const int S = K / KC;
    float4 pa[8], pb[8];

    // prefetch + store chunk 0
#pragma unroll
    for (int j = 0; j < 4; j++) {
        pa[2 * j]     = *(const float4*)(Ag + j * 8);
        pa[2 * j + 1] = *(const float4*)(Ag + j * 8 + 4);
        pb[2 * j]     = *(const float4*)(Bg + j * 8);
        pb[2 * j + 1] = *(const float4*)(Bg + j * 8 + 4);
    }
#pragma unroll
    for (int j = 0; j < 4; j++) {
        uint32_t sw = SW128(fill_base + j * 16);
        cvt_store8(pa[2 * j], pa[2 * j + 1], smem + OFF_AHI, smem + OFF_ALO, sw);
        cvt_store8(pb[2 * j], pb[2 * j + 1], smem + OFF_BHI, smem + OFF_BLO, sw);
    }
    __syncthreads();

    for (int s = 0; s < S; s++) {
        const int buf = s & 1;
        const uint32_t st = sb + buf * STAGE;

        // prefetch chunk s+1 (global -> regs) before compute
        if (s + 1 < S) {
            const float* Ag2 = Ag + (s + 1) * KC;
            const float* Bg2 = Bg + (s + 1) * KC;
#pragma unroll
            for (int j = 0; j < 4; j++) {
                pa[2 * j]     = *(const float4*)(Ag2 + j * 8);
                pa[2 * j + 1] = *(const float4*)(Ag2 + j * 8 + 4);
                pb[2 * j]     = *(const float4*)(Bg2 + j * 8);
                pb[2 * j + 1] = *(const float4*)(Bg2 + j * 8 + 4);
            }
        }

        // compute chunk s
#pragma unroll
        for (int ks = 0; ks < KC / 16; ks++) {
            uint32_t ahi[4][4], alo[4][4];
#pragma unroll
            for (int mt = 0; mt < 4; mt++) {
                uint32_t off = SW128((uint32_t)((wm + mt * 16 + lrow8) * 128 + ks * 32 + lk16));
                ldsm4(ahi[mt], st + OFF_AHI + off);
                ldsm4(alo[mt], st + OFF_ALO + off);
            }
            uint32_t bhi[2][4], blo[2][4];
#pragma unroll
            for (int bt = 0; bt < 2; bt++) {
                uint32_t off = SW128((uint32_t)((wn + bt * 16 + lrow8) * 128 + ks * 32 + lk16));
                ldsm4(bhi[bt], st + OFF_BHI + off);
                ldsm4(blo[bt], st + OFF_BLO + off);
            }
#pragma unroll
            for (int mt = 0; mt < 4; mt++)
#pragma unroll
                for (int nt = 0; nt < 4; nt++) {
                    const int bt = nt >> 1, sub = nt & 1;
                    mma16816(acc[mt][nt], ahi[mt], bhi[bt][sub], bhi[bt][sub + 2]);
                    mma16816(acc[mt][nt], ahi[mt], blo[bt][sub], blo[bt][sub + 2]);
                    mma16816(acc[mt][nt], alo[mt], bhi[bt][sub], bhi[bt][sub + 2]);
                }
        }

        // convert+store chunk s+1 into the other buffer
        if (s + 1 < S) {
            char* base = smem + (buf ^ 1) * STAGE;
#pragma unroll
            for (int j = 0; j < 4; j++) {
                uint32_t sw = SW128(fill_base + j * 16);
                cvt_store8(pa[2 * j], pa[2 * j + 1], base + OFF_AHI, base + OFF_ALO, sw);
                cvt_store8(pb[2 * j], pb[2 * j + 1], base + OFF_BHI, base + OFF_BLO, sw);
            }
        }
        __syncthreads();
    }

    // ------------------------- epilogue -------------------------
    int qlen = 0, clen = 0;
    if (EPI == 1) { qlen = ql[bz]; clen = cl[bz]; }
    const int rq = lane >> 2;           // row within 8
    const int cq = (lane & 3) * 2;      // col within 8

#pragma unroll
    for (int mt = 0; mt < 4; mt++) {
#pragma unroll
        for (int half = 0; half < 2; half++) {
            const int gm = m0 + wm + mt * 16 + rq + half * 8;
            float* crow = C + (long long)gm * ldc;
            const bool rowdead = (EPI == 1) && (gm >= qlen);
#pragma unroll
            for (int nt = 0; nt < 4; nt++) {
                const int gn = n0 + wn + nt * 8 + cq;
                float v0 = acc[mt][nt][half * 2 + 0];
                float v1 = acc[mt][nt][half * 2 + 1];
                if (EPI == 1) {
                    if (rowdead || gn     >= clen) v0 = NEG_INF;
                    if (rowdead || gn + 1 >= clen) v1 = NEG_INF;
                }
                if (EPI == 2) { v0 = tanhf(v0); v1 = tanhf(v1); }
                *(float2*)(crow + gn) = make_float2(v0, v1);
            }
        }
    }
}

// ---------------------------------------------------------------------------
// context transpose: ctxT[b][d][k] = context[b][k][d]
// ---------------------------------------------------------------------------
__global__ __launch_bounds__(256)
void transpose_kernel(const float* __restrict__ src, float* __restrict__ dst)
{
    __shared__ float t[32][33];
    const long long bo = (long long)blockIdx.z * DIM * LK;
    const int x = blockIdx.x * 32 + threadIdx.x;
    const int y = blockIdx.y * 32 + threadIdx.y;
#pragma unroll
    for (int i = 0; i < 32; i += 8)
        t[threadIdx.y + i][threadIdx.x] = src[bo + (long long)(y + i) * DIM + x];
    __syncthreads();
    const int x2 = blockIdx.y * 32 + threadIdx.x;
    const int y2 = blockIdx.x * 32 + threadIdx.y;
#pragma unroll
    for (int i = 0; i < 32; i += 8)
        dst[bo + (long long)(y2 + i) * LK + x2] = t[threadIdx.x][threadIdx.y + i];
}

// ---------------------------------------------------------------------------
// Row softmax over Lk=1024
// ---------------------------------------------------------------------------
__global__ __launch_bounds__(256)
void softmax_kernel(const float* __restrict__ scores, float* __restrict__ weights)
{
    const long long row = blockIdx.x;
    const float* s = scores + row * LK;
    float* w = weights + row * LK;
    const int t = threadIdx.x;

    float v[4];
    float lmax = -INFINITY;
#pragma unroll
    for (int c = 0; c < 4; c++) {
        v[c] = s[t + c * 256];
        lmax = fmaxf(lmax, v[c]);
    }
    __shared__ float red[8];
#pragma unroll
    for (int o = 16; o > 0; o >>= 1) lmax = fmaxf(lmax, __shfl_xor_sync(0xffffffffu, lmax, o));
    if ((t & 31) == 0) red[t >> 5] = lmax;
    __syncthreads();
    if (t < 32) {
        float m = (t < 8) ? red[t] : -INFINITY;
#pragma unroll
        for (int o = 4; o > 0; o >>= 1) m = fmaxf(m, __shfl_xor_sync(0xffffffffu, m, o));
        if (t == 0) red[0] = m;
    }
    __syncthreads();
    const float m = red[0];

    float lsum = 0.f;
#pragma unroll
    for (int c = 0; c < 4; c++) { v[c] = __expf(v[c] - m); lsum += v[c]; }
#pragma unroll
    for (int o = 16; o > 0; o >>= 1) lsum += __shfl_xor_sync(0xffffffffu, lsum, o);
    __shared__ float red2[8];
    if ((t & 31) == 0) red2[t >> 5] = lsum;
    __syncthreads();
    if (t < 32) {
        float x = (t < 8) ? red2[t] : 0.f;
#pragma unroll
        for (int o = 4; o > 0; o >>= 1) x += __shfl_xor_sync(0xffffffffu, x, o);
        if (t == 0) red2[0] = x;
    }
    __syncthreads();
    const float inv = 1.0f / red2[0];
#pragma unroll
    for (int c = 0; c < 4; c++) w[t + c * 256] = v[c] * inv;
}

// ---------------------------------------------------------------------------
extern "C" void kernel_launch(void* const* d_in, const int* in_sizes, int n_in,
                              void* d_out, int out_size)
{
    const float* query   = (const float*)d_in[0];
    const float* context = (const float*)d_in[1];
    const int*   ql      = (const int*)d_in[2];
    const int*   cl      = (const int*)d_in[3];
    const float* W_in    = (const float*)d_in[4];
    const float* W_out   = (const float*)d_in[5];

    float* out        = (float*)d_out;
    float* scores_out = out + (long long)Bsz * LQ * DIM;

    float* combined = nullptr;
    float* weights  = nullptr;
    float* ctxT     = nullptr;
    cudaGetSymbolAddress((void**)&combined, g_combined);
    cudaGetSymbolAddress((void**)&weights,  g_weights);
    cudaGetSymbolAddress((void**)&ctxT,     g_ctxT);

    cudaFuncSetAttribute(mma_gemm<0>, cudaFuncAttributeMaxDynamicSharedMemorySize, SM_TOTAL);
    cudaFuncSetAttribute(mma_gemm<1>, cudaFuncAttributeMaxDynamicSharedMemorySize, SM_TOTAL);
    cudaFuncSetAttribute(mma_gemm<2>, cudaFuncAttributeMaxDynamicSharedMemorySize, SM_TOTAL);

    const long long M_all = (long long)Bsz * LQ;  // 32768

    // T: ctxT = context^T (per batch)
    transpose_kernel<<<dim3(32, 32, Bsz), dim3(32, 8)>>>(context, ctxT);

    // K1: q = query @ W_in^T -> combined cols [D,2D)
    mma_gemm<0><<<dim3(DIM / TN, (unsigned)(M_all / TM), 1), 256, SM_TOTAL>>>(
        query, W_in, combined + DIM, DIM,
        DIM, DIM, 2 * DIM, 0, 0, 0, nullptr, nullptr);

    // K2: scores[b] = q[b] @ context[b]^T, masked -> scores_out (output #2)
    mma_gemm<1><<<dim3(LK / TN, LQ / TM, Bsz), 256, SM_TOTAL>>>(
        combined + DIM, context, scores_out, DIM,
        2 * DIM, DIM, LK,
        (long long)LQ * 2 * DIM, (long long)LK * DIM, (long long)LQ * LK, ql, cl);

    // K3: softmax
    softmax_kernel<<<(unsigned)M_all, 256>>>(scores_out, weights);

    // K4: mix[b] = weights[b] @ ctxT[b]^T -> combined cols [0,D)
    mma_gemm<0><<<dim3(DIM / TN, LQ / TM, Bsz), 256, SM_TOTAL>>>(
        weights, ctxT, combined, LK,
        LK, LK, 2 * DIM,
        (long long)LQ * LK, (long long)DIM * LK, (long long)LQ * 2 * DIM, nullptr, nullptr);

    // K5: out = tanh(combined @ W_out^T)
    mma_gemm<2><<<dim3(DIM / TN, (unsigned)(M_all / TM), 1), 256, SM_TOTAL>>>(
        combined, W_out, out, 2 * DIM,
        2 * DIM, 2 * DIM, DIM, 0, 0, 0, nullptr, nullptr);
}

// round 4
// speedup vs baseline: 2.2009x; 1.4107x over previous
#include <cuda_runtime.h>
#include <cuda_bf16.h>
#include <stdint.h>
#include <math.h>

#define NEG_INF (-1e9f)

#define Bsz 32
#define LQ  1024
#define LK  1024
#define DIM 1024

typedef __nv_bfloat16  bf16;
typedef __nv_bfloat162 bf162;

// ---------------------------------------------------------------------------
// Scratch (__device__ globals; allocation-free rule). All bf16 hi/lo pairs.
// ---------------------------------------------------------------------------
__device__ bf16 g_combh[(long long)Bsz * LQ * 2 * DIM];  // [32768,2048] mix|q
__device__ bf16 g_combl[(long long)Bsz * LQ * 2 * DIM];
__device__ bf16 g_wh[(long long)Bsz * LQ * LK];          // softmax weights
__device__ bf16 g_wl[(long long)Bsz * LQ * LK];
__device__ bf16 g_qryh[(long long)Bsz * LQ * DIM];
__device__ bf16 g_qryl[(long long)Bsz * LQ * DIM];
__device__ bf16 g_ctxh[(long long)Bsz * LK * DIM];
__device__ bf16 g_ctxl[(long long)Bsz * LK * DIM];
__device__ bf16 g_ctxTh[(long long)Bsz * DIM * LK];
__device__ bf16 g_ctxTl[(long long)Bsz * DIM * LK];
__device__ bf16 g_winh[DIM * DIM];
__device__ bf16 g_winl[DIM * DIM];
__device__ bf16 g_wouth[DIM * 2 * DIM];
__device__ bf16 g_woutl[DIM * 2 * DIM];

// ---------------------------------------------------------------------------
#define SW128(off) ((off) ^ (((off) >> 3) & 0x70))

__device__ __forceinline__ uint32_t smem_u32(const void* p) {
    uint32_t a;
    asm("{ .reg .u64 t; cvta.to.shared.u64 t, %1; cvt.u32.u64 %0, t; }"
        : "=r"(a) : "l"(p));
    return a;
}
__device__ __forceinline__ void cp16(uint32_t dst, const void* src) {
    asm volatile("cp.async.cg.shared.global [%0], [%1], 16;"
                 :: "r"(dst), "l"(src) : "memory");
}
#define CP_COMMIT() asm volatile("cp.async.commit_group;" ::: "memory")
#define CP_WAIT1()  asm volatile("cp.async.wait_group 1;" ::: "memory")

__device__ __forceinline__ void ldsm4(uint32_t* r, uint32_t addr) {
    asm volatile("ldmatrix.sync.aligned.m8n8.x4.shared.b16 {%0,%1,%2,%3}, [%4];"
                 : "=r"(r[0]), "=r"(r[1]), "=r"(r[2]), "=r"(r[3]) : "r"(addr));
}
__device__ __forceinline__ void mma16816(float* c, const uint32_t* a,
                                         uint32_t b0, uint32_t b1) {
    asm volatile(
        "mma.sync.aligned.m16n8k16.row.col.f32.bf16.bf16.f32 "
        "{%0,%1,%2,%3}, {%4,%5,%6,%7}, {%8,%9}, {%0,%1,%2,%3};"
        : "+f"(c[0]), "+f"(c[1]), "+f"(c[2]), "+f"(c[3])
        : "r"(a[0]), "r"(a[1]), "r"(a[2]), "r"(a[3]), "r"(b0), "r"(b1));
}

__device__ __forceinline__ void split2(float a, float b, bf162& hi, bf162& lo) {
    hi = __floats2bfloat162_rn(a, b);
    float2 hf = __bfloat1622float2(hi);
    lo = __floats2bfloat162_rn(a - hf.x, b - hf.y);
}

// ---------------------------------------------------------------------------
// Tile geometry: CTA 128x128, K-chunk 64 bf16 (128B rows, SW128), 256 threads.
// Stage: Ahi|Alo|Bhi|Blo, 16KB each = 64KB. 3 stages = 192KB.
// ---------------------------------------------------------------------------
#define TM 128
#define TN 128
#define KC 64
#define OFF_AHI   0
#define OFF_ALO   16384
#define OFF_BHI   32768
#define OFF_BLO   49152
#define STAGE     65536
#define NSTAGE    3
#define SM_TOTAL  (NSTAGE * STAGE)   // 196608

// ---------------------------------------------------------------------------
// split-bf16 mma.sync GEMM: C[m,n] = sum_k A[m,k]*B[n,k]  (pre-split operands)
// EPI: 0 = split-bf16 out (Chi/Clo), 1 = length-mask fp32 out, 2 = tanh fp32 out
// ---------------------------------------------------------------------------
template <int EPI>
__global__ __launch_bounds__(256, 1)
void mma_gemm(const bf16* __restrict__ Ahi, const bf16* __restrict__ Alo,
              const bf16* __restrict__ Bhi, const bf16* __restrict__ Blo,
              float* __restrict__ Cf, bf16* __restrict__ Chi, bf16* __restrict__ Clo,
              int K, int lda, int ldb, int ldc,
              long long sA, long long sB, long long sC,
              const int* __restrict__ ql, const int* __restrict__ cl)
{
    extern __shared__ char smem[];
    const uint32_t sb = smem_u32(smem);
    const int tid  = threadIdx.x;
    const int wid  = tid >> 5;
    const int lane = tid & 31;
    const int bz = blockIdx.z;
    const int m0 = blockIdx.y * TM;
    const int n0 = blockIdx.x * TN;

    Ahi += (long long)bz * sA;  Alo += (long long)bz * sA;
    Bhi += (long long)bz * sB;  Blo += (long long)bz * sB;

    // fill mapping: thread -> row = tid/2, col half = (tid&1)*32 elems; 4 x 16B
    const int lrow  = tid >> 1;
    const int lhalf = (tid & 1) * 32;
    const bf16* Ah = Ahi + (long long)(m0 + lrow) * lda + lhalf;
    const bf16* Al = Alo + (long long)(m0 + lrow) * lda + lhalf;
    const bf16* Bh = Bhi + (long long)(n0 + lrow) * ldb + lhalf;
    const bf16* Bl = Blo + (long long)(n0 + lrow) * ldb + lhalf;
    const uint32_t fb = (uint32_t)(lrow * 128 + (tid & 1) * 64);

    const int S = K / KC;

    auto issue = [&](int s) {
        const uint32_t st = sb + (s % NSTAGE) * STAGE;
        const int k0 = s * KC;
#pragma unroll
        for (int j = 0; j < 4; j++) {
            const uint32_t sw = SW128(fb + j * 16);
            cp16(st + OFF_AHI + sw, Ah + k0 + j * 8);
            cp16(st + OFF_ALO + sw, Al + k0 + j * 8);
            cp16(st + OFF_BHI + sw, Bh + k0 + j * 8);
            cp16(st + OFF_BLO + sw, Bl + k0 + j * 8);
        }
        CP_COMMIT();
    };

    issue(0);
    issue(1);

    // warp tile: 64x32 (warp grid 2x4)
    const int wm = (wid & 1) * 64;
    const int wn = (wid >> 1) * 32;
    const int lrow8 = (lane & 7) + ((lane >> 3) & 1) * 8;
    const int lk16  = ((lane >> 4) & 1) * 16;

    float acc[4][4][4];
#pragma unroll
    for (int mt = 0; mt < 4; mt++)
#pragma unroll
        for (int nt = 0; nt < 4; nt++)
#pragma unroll
            for (int i = 0; i < 4; i++) acc[mt][nt][i] = 0.f;

    for (int s = 0; s < S; s++) {
        CP_WAIT1();
        __syncthreads();
        if (s + 2 < S) issue(s + 2);

        const uint32_t st = sb + (s % NSTAGE) * STAGE;
#pragma unroll
        for (int ks = 0; ks < KC / 16; ks++) {
            uint32_t ahi[4][4], alo[4][4];
#pragma unroll
            for (int mt = 0; mt < 4; mt++) {
                uint32_t off = SW128((uint32_t)((wm + mt * 16 + lrow8) * 128 + ks * 32 + lk16));
                ldsm4(ahi[mt], st + OFF_AHI + off);
                ldsm4(alo[mt], st + OFF_ALO + off);
            }
            uint32_t bhi[2][4], blo[2][4];
#pragma unroll
            for (int bt = 0; bt < 2; bt++) {
                uint32_t off = SW128((uint32_t)((wn + bt * 16 + lrow8) * 128 + ks * 32 + lk16));
                ldsm4(bhi[bt], st + OFF_BHI + off);
                ldsm4(blo[bt], st + OFF_BLO + off);
            }
#pragma unroll
            for (int mt = 0; mt < 4; mt++)
#pragma unroll
                for (int nt = 0; nt < 4; nt++) {
                    const int bt = nt >> 1, sub = nt & 1;
                    mma16816(acc[mt][nt], ahi[mt], bhi[bt][sub], bhi[bt][sub + 2]);
                    mma16816(acc[mt][nt], ahi[mt], blo[bt][sub], blo[bt][sub + 2]);
                    mma16816(acc[mt][nt], alo[mt], bhi[bt][sub], bhi[bt][sub + 2]);
                }
        }
        __syncthreads();
    }

    // ------------------------- epilogue -------------------------
    int qlen = 0, clen = 0;
    if (EPI == 1) { qlen = ql[bz]; clen = cl[bz]; }
    const int rq = lane >> 2;
    const int cq = (lane & 3) * 2;

#pragma unroll
    for (int mt = 0; mt < 4; mt++) {
#pragma unroll
        for (int half = 0; half < 2; half++) {
            const int gm = m0 + wm + mt * 16 + rq + half * 8;
            const bool rowdead = (EPI == 1) && (gm >= qlen);
#pragma unroll
            for (int nt = 0; nt < 4; nt++) {
                const int gn = n0 + wn + nt * 8 + cq;
                float v0 = acc[mt][nt][half * 2 + 0];
                float v1 = acc[mt][nt][half * 2 + 1];
                if (EPI == 0) {
                    bf162 hp, lp;
                    split2(v0, v1, hp, lp);
                    const long long o = (long long)((long long)bz * sC) + (long long)gm * ldc + gn;
                    *(bf162*)(Chi + o) = hp;
                    *(bf162*)(Clo + o) = lp;
                } else {
                    if (EPI == 1) {
                        if (rowdead || gn     >= clen) v0 = NEG_INF;
                        if (rowdead || gn + 1 >= clen) v1 = NEG_INF;
                    }
                    if (EPI == 2) { v0 = tanhf(v0); v1 = tanhf(v1); }
                    const long long o = (long long)((long long)bz * sC) + (long long)gm * ldc + gn;
                    *(float2*)(Cf + o) = make_float2(v0, v1);
                }
            }
        }
    }
}

// ---------------------------------------------------------------------------
// elementwise fp32 -> (hi, lo) bf16 split. n multiple of 4.
// ---------------------------------------------------------------------------
__global__ __launch_bounds__(256)
void convert_split(const float4* __restrict__ src, bf162* __restrict__ hi,
                   bf162* __restrict__ lo, long long n4)
{
    const long long i = (long long)blockIdx.x * blockDim.x + threadIdx.x;
    if (i >= n4) return;
    float4 v = src[i];
    bf162 h0, l0, h1, l1;
    split2(v.x, v.y, h0, l0);
    split2(v.z, v.w, h1, l1);
    hi[2 * i] = h0; hi[2 * i + 1] = h1;
    lo[2 * i] = l0; lo[2 * i + 1] = l1;
}

// ---------------------------------------------------------------------------
// context: split-convert AND transposed split-convert in one pass.
// ---------------------------------------------------------------------------
__global__ __launch_bounds__(256)
void transpose_convert(const float* __restrict__ src,
                       bf16* __restrict__ ch, bf16* __restrict__ cl_,
                       bf16* __restrict__ th, bf16* __restrict__ tl)
{
    __shared__ float t[32][33];
    const long long bo = (long long)blockIdx.z * LK * DIM;
    const int x = blockIdx.x * 32 + threadIdx.x;
    const int y = blockIdx.y * 32 + threadIdx.y;
#pragma unroll
    for (int i = 0; i < 32; i += 8) {
        float v = src[bo + (long long)(y + i) * DIM + x];
        t[threadIdx.y + i][threadIdx.x] = v;
        bf16 h = __float2bfloat16_rn(v);
        bf16 l = __float2bfloat16_rn(v - __bfloat162float(h));
        ch[bo + (long long)(y + i) * DIM + x] = h;
        cl_[bo + (long long)(y + i) * DIM + x] = l;
    }
    __syncthreads();
    const int x2 = blockIdx.y * 32 + threadIdx.x;   // over LK
    const int y2 = blockIdx.x * 32 + threadIdx.y;   // over DIM
#pragma unroll
    for (int i = 0; i < 32; i += 8) {
        float v = t[threadIdx.x][threadIdx.y + i];
        bf16 h = __float2bfloat16_rn(v);
        bf16 l = __float2bfloat16_rn(v - __bfloat162float(h));
        th[bo + (long long)(y2 + i) * LK + x2] = h;
        tl[bo + (long long)(y2 + i) * LK + x2] = l;
    }
}

// ---------------------------------------------------------------------------
// Row softmax over Lk=1024; emits split bf16 weights.
// ---------------------------------------------------------------------------
__global__ __launch_bounds__(256)
void softmax_kernel(const float* __restrict__ scores,
                    bf16* __restrict__ wh, bf16* __restrict__ wl)
{
    const long long row = blockIdx.x;
    const float* s = scores + row * LK;
    const int t = threadIdx.x;

    float2 x0 = *(const float2*)(s + 2 * t);
    float2 x1 = *(const float2*)(s + 2 * t + 512);
    float lmax = fmaxf(fmaxf(x0.x, x0.y), fmaxf(x1.x, x1.y));

    __shared__ float red[8];
#pragma unroll
    for (int o = 16; o > 0; o >>= 1) lmax = fmaxf(lmax, __shfl_xor_sync(0xffffffffu, lmax, o));
    if ((t & 31) == 0) red[t >> 5] = lmax;
    __syncthreads();
    if (t < 32) {
        float m = (t < 8) ? red[t] : -INFINITY;
#pragma unroll
        for (int o = 4; o > 0; o >>= 1) m = fmaxf(m, __shfl_xor_sync(0xffffffffu, m, o));
        if (t == 0) red[0] = m;
    }
    __syncthreads();
    const float m = red[0];

    float e0 = __expf(x0.x - m), e1 = __expf(x0.y - m);
    float e2 = __expf(x1.x - m), e3 = __expf(x1.y - m);
    float lsum = e0 + e1 + e2 + e3;
#pragma unroll
    for (int o = 16; o > 0; o >>= 1) lsum += __shfl_xor_sync(0xffffffffu, lsum, o);
    __shared__ float red2[8];
    if ((t & 31) == 0) red2[t >> 5] = lsum;
    __syncthreads();
    if (t < 32) {
        float x = (t < 8) ? red2[t] : 0.f;
#pragma unroll
        for (int o = 4; o > 0; o >>= 1) x += __shfl_xor_sync(0xffffffffu, x, o);
        if (t == 0) red2[0] = x;
    }
    __syncthreads();
    const float inv = 1.0f / red2[0];

    bf162 h, l;
    split2(e0 * inv, e1 * inv, h, l);
    *(bf162*)(wh + row * LK + 2 * t) = h;
    *(bf162*)(wl + row * LK + 2 * t) = l;
    split2(e2 * inv, e3 * inv, h, l);
    *(bf162*)(wh + row * LK + 2 * t + 512) = h;
    *(bf162*)(wl + row * LK + 2 * t + 512) = l;
}

// ---------------------------------------------------------------------------
extern "C" void kernel_launch(void* const* d_in, const int* in_sizes, int n_in,
                              void* d_out, int out_size)
{
    const float* query   = (const float*)d_in[0];
    const float* context = (const float*)d_in[1];
    const int*   ql      = (const int*)d_in[2];
    const int*   cl      = (const int*)d_in[3];
    const float* W_in    = (const float*)d_in[4];
    const float* W_out   = (const float*)d_in[5];

    float* out        = (float*)d_out;
    float* scores_out = out + (long long)Bsz * LQ * DIM;

    bf16 *combh, *combl, *wh, *wl, *qryh, *qryl, *ctxh, *ctxl, *ctxTh, *ctxTl;
    bf16 *winh, *winl, *wouth, *woutl;
    cudaGetSymbolAddress((void**)&combh, g_combh);
    cudaGetSymbolAddress((void**)&combl, g_combl);
    cudaGetSymbolAddress((void**)&wh,    g_wh);
    cudaGetSymbolAddress((void**)&wl,    g_wl);
    cudaGetSymbolAddress((void**)&qryh,  g_qryh);
    cudaGetSymbolAddress((void**)&qryl,  g_qryl);
    cudaGetSymbolAddress((void**)&ctxh,  g_ctxh);
    cudaGetSymbolAddress((void**)&ctxl,  g_ctxl);
    cudaGetSymbolAddress((void**)&ctxTh, g_ctxTh);
    cudaGetSymbolAddress((void**)&ctxTl, g_ctxTl);
    cudaGetSymbolAddress((void**)&winh,  g_winh);
    cudaGetSymbolAddress((void**)&winl,  g_winl);
    cudaGetSymbolAddress((void**)&wouth, g_wouth);
    cudaGetSymbolAddress((void**)&woutl, g_woutl);

    cudaFuncSetAttribute(mma_gemm<0>, cudaFuncAttributeMaxDynamicSharedMemorySize, SM_TOTAL);
    cudaFuncSetAttribute(mma_gemm<1>, cudaFuncAttributeMaxDynamicSharedMemorySize, SM_TOTAL);
    cudaFuncSetAttribute(mma_gemm<2>, cudaFuncAttributeMaxDynamicSharedMemorySize, SM_TOTAL);

    const long long M_all = (long long)Bsz * LQ;  // 32768

    // conversions
    {
        long long n4 = (long long)Bsz * LQ * DIM / 4;
        convert_split<<<(unsigned)((n4 + 255) / 256), 256>>>(
            (const float4*)query, (bf162*)qryh, (bf162*)qryl, n4);
        long long w4 = (long long)DIM * DIM / 4;
        convert_split<<<(unsigned)((w4 + 255) / 256), 256>>>(
            (const float4*)W_in, (bf162*)winh, (bf162*)winl, w4);
        long long o4 = (long long)DIM * 2 * DIM / 4;
        convert_split<<<(unsigned)((o4 + 255) / 256), 256>>>(
            (const float4*)W_out, (bf162*)wouth, (bf162*)woutl, o4);
        transpose_convert<<<dim3(32, 32, Bsz), dim3(32, 8)>>>(
            context, ctxh, ctxl, ctxTh, ctxTl);
    }

    // K1: q = query @ W_in^T -> comb cols [D,2D) (split)
    mma_gemm<0><<<dim3(DIM / TN, (unsigned)(M_all / TM), 1), 256, SM_TOTAL>>>(
        qryh, qryl, winh, winl, nullptr, combh + DIM, combl + DIM,
        DIM, DIM, DIM, 2 * DIM, 0, 0, 0, nullptr, nullptr);

    // K2: scores[b] = q[b] @ ctx[b]^T, masked fp32 -> scores_out
    mma_gemm<1><<<dim3(LK / TN, LQ / TM, Bsz), 256, SM_TOTAL>>>(
        combh + DIM, combl + DIM, ctxh, ctxl, scores_out, nullptr, nullptr,
        DIM, 2 * DIM, DIM, LK,
        (long long)LQ * 2 * DIM, (long long)LK * DIM, (long long)LQ * LK, ql, cl);

    // K3: softmax -> split weights
    softmax_kernel<<<(unsigned)M_all, 256>>>(scores_out, wh, wl);

    // K4: mix[b] = weights[b] @ ctxT[b]^T -> comb cols [0,D) (split)
    mma_gemm<0><<<dim3(DIM / TN, LQ / TM, Bsz), 256, SM_TOTAL>>>(
        wh, wl, ctxTh, ctxTl, nullptr, combh, combl,
        LK, LK, LK, 2 * DIM,
        (long long)LQ * LK, (long long)DIM * LK, (long long)LQ * 2 * DIM, nullptr, nullptr);

    // K5: out = tanh(comb @ W_out^T) fp32
    mma_gemm<2><<<dim3(DIM / TN, (unsigned)(M_all / TM), 1), 256, SM_TOTAL>>>(
        combh, combl, wouth, woutl, out, nullptr, nullptr,
        2 * DIM, 2 * DIM, 2 * DIM, DIM, 0, 0, 0, nullptr, nullptr);
}